// round 11
// baseline (speedup 1.0000x reference)
#include <cuda_runtime.h>
#include <cuda_bf16.h>
#include <math.h>
#include <stdint.h>

// Problem constants
#define BATCH   2
#define SEQ     2048
#define CDIM    1024
#define NHEAD   16
#define HDIM    64
#define C3      3072
#define MROWS   4096            // BATCH*SEQ
#define KEFF    3072            // split-bf16 effective K (= 3*CDIM)
#define NCHUNK  48              // KEFF / 64
#define NBH     32              // BATCH*NHEAD

// Scratch (device globals — no runtime allocation allowed)
__device__ float g_v32[MROWS * CDIM];                  // V (fp32) from QKV gemm
__device__ __nv_bfloat16 g_abig[MROWS * KEFF];         // split A: [hi | lo | hi]
__device__ __nv_bfloat16 g_wqkvt[C3 * KEFF];           // W_qkv^T split: [hi | hi | lo]
__device__ __nv_bfloat16 g_wprojt[CDIM * KEFF];        // W_proj^T split: [hi | hi | lo]
// per-head split attention operands
__device__ __nv_bfloat16 g_q[NBH * 2 * SEQ * HDIM];    // [bh][hi/lo][t][d]
__device__ __nv_bfloat16 g_k[NBH * 2 * SEQ * HDIM];    // [bh][hi/lo][t][d]
__device__ __nv_bfloat16 g_vt[NBH * 2 * HDIM * SEQ];   // [bh][hi/lo][d][t]

// ---------------------------------------------------------------------------
// Helpers (base-sm_100-legal PTX only)
// ---------------------------------------------------------------------------
__device__ __forceinline__ uint32_t smem_u32(const void* p) {
    uint32_t a;
    asm("{ .reg .u64 t; cvta.to.shared.u64 t, %1; cvt.u32.u64 %0, t; }" : "=r"(a) : "l"(p));
    return a;
}
__device__ __forceinline__ void cp_async16(uint32_t dst, const void* src) {
    asm volatile("cp.async.cg.shared.global [%0], [%1], 16;" :: "r"(dst), "l"(src));
}
#define CP_COMMIT()  asm volatile("cp.async.commit_group;")
#define CP_WAIT(n)   asm volatile("cp.async.wait_group %0;" :: "n"(n))

__device__ __forceinline__ void ldmx4(uint32_t* r, uint32_t addr) {
    asm volatile("ldmatrix.sync.aligned.m8n8.x4.shared.b16 {%0,%1,%2,%3}, [%4];"
                 : "=r"(r[0]), "=r"(r[1]), "=r"(r[2]), "=r"(r[3]) : "r"(addr));
}
__device__ __forceinline__ void mma16816(float* d, const uint32_t* a, const uint32_t* b) {
    asm volatile("mma.sync.aligned.m16n8k16.row.col.f32.bf16.bf16.f32 "
                 "{%0,%1,%2,%3}, {%4,%5,%6,%7}, {%8,%9}, {%0,%1,%2,%3};"
                 : "+f"(d[0]), "+f"(d[1]), "+f"(d[2]), "+f"(d[3])
                 : "r"(a[0]), "r"(a[1]), "r"(a[2]), "r"(a[3]), "r"(b[0]), "r"(b[1]));
}
__device__ __forceinline__ uint32_t packbf2(float x, float y) {
    const __nv_bfloat162 v = __floats2bfloat162_rn(x, y);   // x -> low half
    return *(const uint32_t*)&v;
}
#define SWZ(o) ((o) ^ (((o) >> 3) & 0x70))

// ---------------------------------------------------------------------------
// fp32 [M][1024] -> split bf16 [M][3072] = [hi | lo | hi]  (GEMM A side)
// ---------------------------------------------------------------------------
__global__ void __launch_bounds__(256)
conv_split_kernel(const float* __restrict__ in, __nv_bfloat16* __restrict__ out)
{
    const int idx = blockIdx.x * 256 + threadIdx.x;
    const int m = idx >> 10;
    const int k = idx & 1023;
    const float a = in[idx];
    const __nv_bfloat16 hi = __float2bfloat16(a);
    const __nv_bfloat16 lo = __float2bfloat16(a - __bfloat162float(hi));
    __nv_bfloat16* row = out + (size_t)m * KEFF;
    row[k]            = hi;
    row[CDIM + k]     = lo;
    row[2 * CDIM + k] = hi;
}

// ---------------------------------------------------------------------------
// Weight transpose + split: w [1024][Nw] -> out [Nw][3072] = [hi | hi | lo]
// ---------------------------------------------------------------------------
__global__ void __launch_bounds__(1024)
conv_wt_kernel(const float* __restrict__ w, __nv_bfloat16* __restrict__ out, int Nw)
{
    __shared__ float tile[32][33];
    const int n0 = blockIdx.x * 32;
    const int k0 = blockIdx.y * 32;
    tile[threadIdx.y][threadIdx.x] = w[(size_t)(k0 + threadIdx.y) * Nw + n0 + threadIdx.x];
    __syncthreads();
    const int n = n0 + threadIdx.y;
    const int k = k0 + threadIdx.x;
    const float a = tile[threadIdx.x][threadIdx.y];
    const __nv_bfloat16 hi = __float2bfloat16(a);
    const __nv_bfloat16 lo = __float2bfloat16(a - __bfloat162float(hi));
    __nv_bfloat16* row = out + (size_t)n * KEFF;
    row[k]            = hi;
    row[CDIM + k]     = hi;
    row[2 * CDIM + k] = lo;
}

// ---------------------------------------------------------------------------
// Attention prep: transposed split V   g_vt[bh][seg][d][t]   (reads g_v32)
// ---------------------------------------------------------------------------
__global__ void __launch_bounds__(1024)
prep_vt_kernel()
{
    __shared__ float tile[32][33];
    const int bh = blockIdx.z;
    const int b  = bh >> 4;
    const int h  = bh & 15;
    const int t0 = blockIdx.x * 32;
    const int d0 = blockIdx.y * 32;

    tile[threadIdx.y][threadIdx.x] =
        g_v32[(size_t)(b * SEQ + t0 + threadIdx.y) * CDIM + h * HDIM + d0 + threadIdx.x];
    __syncthreads();
    const int d = d0 + threadIdx.y;
    const int t = t0 + threadIdx.x;
    const float v = tile[threadIdx.x][threadIdx.y];
    const __nv_bfloat16 hi = __float2bfloat16(v);
    const __nv_bfloat16 lo = __float2bfloat16(v - __bfloat162float(hi));
    g_vt[((size_t)(bh * 2 + 0) * HDIM + d) * SEQ + t] = hi;
    g_vt[((size_t)(bh * 2 + 1) * HDIM + d) * SEQ + t] = lo;
}

// ---------------------------------------------------------------------------
// Tensor-core bf16 GEMM — PERSISTENT tile loop (fixes wave quantization):
// grid = min(296, ntiles); each CTA processes tiles blockIdx.x, +gridDim.x,...
// Per tile: 3-stage cp.async pipeline, 1 sync per chunk, KEFF=3072.
// mode 0: out = A*Bt + bias (fp32). mode 1: QKV epilogue split writes.
// ---------------------------------------------------------------------------
#define GEMM_DYN_SMEM (3 * 32768)

__global__ void __launch_bounds__(256, 2)
gemm_mma_kernel(const __nv_bfloat16* __restrict__ A, const __nv_bfloat16* __restrict__ Bt,
                const float* __restrict__ bias, float* __restrict__ out, int Nout,
                int mode, int ntiles)
{
    extern __shared__ __align__(1024) char dyn[];
    const uint32_t tiles = smem_u32(dyn);

    const int tid = threadIdx.x;
    const int wid = tid >> 5;
    const int lane = tid & 31;
    const int wm = wid & 1;
    const int wn = wid >> 1;
    const int ncols = Nout >> 7;

    const int l15 = lane & 15;
    const int lhi16 = (lane >> 4) * 16;
    const int b_row = ((lane & 16) >> 1) + (lane & 7);
    const int b_khalf = (lane & 8) ? 16 : 0;
    const int tr = lane >> 2;
    const int tc = (lane & 3) * 2;

    for (int tile = blockIdx.x; tile < ntiles; tile += gridDim.x) {
        const int m0 = (tile / ncols) * 128;
        const int n0 = (tile % ncols) * 128;

        const __nv_bfloat16* Arow = A  + (size_t)m0 * KEFF;
        const __nv_bfloat16* Brow = Bt + (size_t)n0 * KEFF;

        auto load_chunk = [&](int c, int buf) {
            const uint32_t abase = tiles + buf * 32768;
            const uint32_t bbase = abase + 16384;
            const __nv_bfloat16* ag = Arow + c * 64;
            const __nv_bfloat16* bg = Brow + c * 64;
#pragma unroll
            for (int i = 0; i < 4; ++i) {
                const int g   = tid + 256 * i;
                const int row = g >> 3;
                const int gc  = g & 7;
                const uint32_t off = SWZ((uint32_t)(row * 128 + gc * 16));
                cp_async16(abase + off, (const char*)(ag + (size_t)row * KEFF) + gc * 16);
                cp_async16(bbase + off, (const char*)(bg + (size_t)row * KEFF) + gc * 16);
            }
            CP_COMMIT();
        };

        float acc[4][4][4];
#pragma unroll
        for (int mi = 0; mi < 4; ++mi)
#pragma unroll
            for (int ni = 0; ni < 4; ++ni)
#pragma unroll
                for (int r = 0; r < 4; ++r) acc[mi][ni][r] = 0.f;

        load_chunk(0, 0);
        load_chunk(1, 1);

        int buf = 0;
        for (int c = 0; c < NCHUNK; ++c) {
            if (c < NCHUNK - 1) { CP_WAIT(1); } else { CP_WAIT(0); }
            __syncthreads();
            if (c + 2 < NCHUNK) {
                int nb = buf + 2; if (nb >= 3) nb -= 3;
                load_chunk(c + 2, nb);
            }

            const uint32_t abase = tiles + buf * 32768;
            const uint32_t bbase = abase + 16384;

#pragma unroll
            for (int ks = 0; ks < 4; ++ks) {
                const int kb = ks * 32;
                uint32_t afr[4][4];
#pragma unroll
                for (int mi = 0; mi < 4; ++mi) {
                    const int row = wm * 64 + mi * 16 + l15;
                    ldmx4(afr[mi], abase + SWZ((uint32_t)(row * 128 + kb + lhi16)));
                }
                uint32_t bfr[2][4];
#pragma unroll
                for (int nj = 0; nj < 2; ++nj) {
                    const int row = wn * 32 + nj * 16 + b_row;
                    ldmx4(bfr[nj], bbase + SWZ((uint32_t)(row * 128 + kb + b_khalf)));
                }
#pragma unroll
                for (int mi = 0; mi < 4; ++mi) {
#pragma unroll
                    for (int ni = 0; ni < 4; ++ni)
                        mma16816(acc[mi][ni], afr[mi], &bfr[ni >> 1][(ni & 1) * 2]);
                }
            }
            if (++buf >= 3) buf = 0;
        }
        __syncthreads();   // smem quiescent before next tile's loads

        auto wsplit = [&](__nv_bfloat16* basep, int gr_, int cc, float a0, float a1) {
            const int t  = gr_ & (SEQ - 1);
            const int bb = gr_ >> 11;
            const int hh = cc >> 6;
            const int dd = cc & 63;
            const int bhx = bb * NHEAD + hh;
            const __nv_bfloat16 h0 = __float2bfloat16(a0);
            const __nv_bfloat16 h1 = __float2bfloat16(a1);
            const __nv_bfloat16 l0 = __float2bfloat16(a0 - __bfloat162float(h0));
            const __nv_bfloat16 l1 = __float2bfloat16(a1 - __bfloat162float(h1));
            *(__nv_bfloat162*)(basep + ((size_t)(bhx * 2 + 0) * SEQ + t) * HDIM + dd) = __nv_bfloat162(h0, h1);
            *(__nv_bfloat162*)(basep + ((size_t)(bhx * 2 + 1) * SEQ + t) * HDIM + dd) = __nv_bfloat162(l0, l1);
        };

#pragma unroll
        for (int mi = 0; mi < 4; ++mi) {
#pragma unroll
            for (int ni = 0; ni < 4; ++ni) {
                const int gr = m0 + wm * 64 + mi * 16 + tr;
                const int gc = n0 + wn * 32 + ni * 8 + tc;
                const float b0 = bias[gc], b1 = bias[gc + 1];
                const float y00 = acc[mi][ni][0] + b0, y01 = acc[mi][ni][1] + b1;
                const float y10 = acc[mi][ni][2] + b0, y11 = acc[mi][ni][3] + b1;
                if (mode == 0) {
                    *(float2*)(out + (size_t)gr * Nout + gc)       = make_float2(y00, y01);
                    *(float2*)(out + (size_t)(gr + 8) * Nout + gc) = make_float2(y10, y11);
                } else {
                    if (gc < CDIM) {
                        wsplit(g_q, gr, gc, y00, y01);
                        wsplit(g_q, gr + 8, gc, y10, y11);
                    } else if (gc < 2 * CDIM) {
                        wsplit(g_k, gr, gc - CDIM, y00, y01);
                        wsplit(g_k, gr + 8, gc - CDIM, y10, y11);
                    } else {
                        const int cc = gc - 2 * CDIM;
                        *(float2*)(g_v32 + (size_t)gr * CDIM + cc)       = make_float2(y00, y01);
                        *(float2*)(g_v32 + (size_t)(gr + 8) * CDIM + cc) = make_float2(y10, y11);
                    }
                }
            }
        }
    }
}

// ---------------------------------------------------------------------------
// Tensor-core flash attention (R8-exact, best known ~533 total):
// Q-tile 128, 8 warps x 16 rows; Q fragments register-resident; P converted
// to bf16 hi/lo in registers and fed directly as mma A operand.
// 3-stage KV pipeline, 1 sync per kt. No reg cap (no min-blocks).
// ---------------------------------------------------------------------------
#define ATT3_SMEM (3 * 32768)

__global__ void __launch_bounds__(256)
attention_tc_kernel()
{
    extern __shared__ __align__(1024) char dyn[];
    const uint32_t sb = smem_u32(dyn);
    const int tid  = threadIdx.x;
    const int wid  = tid >> 5;
    const int lane = tid & 31;

    const int qi = gridDim.x - 1 - blockIdx.x;   // heavy tiles first
    const int bh = blockIdx.y;
    const int b  = bh >> 4;
    const int h  = bh & 15;

    const int l15 = lane & 15;
    const int lhi16 = (lane >> 4) * 16;
    const int b_row = ((lane & 16) >> 1) + (lane & 7);
    const int b_khalf = (lane & 8) ? 16 : 0;
    const int tr = lane >> 2;
    const int tc2 = (lane & 3) * 2;

    // ---- stage Q (hi/lo): 2 segs x 128 rows x 128B into stage0/1 ----
#pragma unroll
    for (int i = 0; i < 8; ++i) {
        const int g = tid + 256 * i;          // 0..2047
        const int seg = g >> 10;
        const int r   = (g >> 3) & 127;
        const int gc  = g & 7;
        const uint32_t dst = sb + seg * 16384 + SWZ((uint32_t)(r * 128 + gc * 16));
        const char* src = (const char*)&g_q[((size_t)(bh * 2 + seg) * SEQ + qi * 128 + r) * HDIM] + gc * 16;
        cp_async16(dst, src);
    }
    CP_COMMIT(); CP_WAIT(0);
    __syncthreads();

    // ---- Q fragments into registers (warp owns rows 16*wid..16*wid+15) ----
    uint32_t qHi[4][4], qLo[4][4];
#pragma unroll
    for (int kb = 0; kb < 4; ++kb) {
        const uint32_t off = SWZ((uint32_t)((16 * wid + l15) * 128 + kb * 32 + lhi16));
        ldmx4(qHi[kb], sb + off);
        ldmx4(qLo[kb], sb + 16384 + off);
    }
    __syncthreads();   // everyone done reading stage0/1 before KV overwrites

    // KV stage loader
    auto load_kv = [&](int kt, int buf) {
        const uint32_t stage = sb + buf * 32768;
#pragma unroll
        for (int i = 0; i < 8; ++i) {
            const int g = tid + 256 * i;      // 0..2047
            const int half = g >> 10;         // 0=K, 1=Vt
            const int seg  = (g >> 9) & 1;
            const int r    = (g >> 3) & 63;
            const int gc   = g & 7;
            const uint32_t dst = stage + half * 16384 + seg * 8192 + SWZ((uint32_t)(r * 128 + gc * 16));
            const char* src = (half == 0)
                ? (const char*)&g_k[((size_t)(bh * 2 + seg) * SEQ + kt * 64 + r) * HDIM] + gc * 16
                : (const char*)&g_vt[((size_t)(bh * 2 + seg) * HDIM + r) * SEQ + kt * 64] + gc * 16;
            cp_async16(dst, src);
        }
        CP_COMMIT();
    };

    const int last = 2 * qi + 1;
    load_kv(0, 0);
    load_kv(1, 1);

    float o[8][4];
#pragma unroll
    for (int ni = 0; ni < 8; ++ni)
#pragma unroll
        for (int r = 0; r < 4; ++r) o[ni][r] = 0.f;
    float m0 = -INFINITY, m1 = -INFINITY;
    float l0 = 0.f, l1 = 0.f;

    const int rowG0 = qi * 128 + 16 * wid + tr;
    const int rowG1 = rowG0 + 8;

    int buf = 0;
    for (int kt = 0; kt <= last; ++kt) {
        if (kt < last) { CP_WAIT(1); } else { CP_WAIT(0); }
        __syncthreads();
        if (kt + 2 <= last) {
            int nb = buf + 2; if (nb >= 3) nb -= 3;
            load_kv(kt + 2, nb);
        }
        const uint32_t stage = sb + buf * 32768;

        // ---- S = Q K^T (3-term split) ----
        float sacc[8][4];
#pragma unroll
        for (int ni = 0; ni < 8; ++ni)
#pragma unroll
            for (int r = 0; r < 4; ++r) sacc[ni][r] = 0.f;

#pragma unroll
        for (int kb = 0; kb < 4; ++kb) {
            const int kbb = kb * 32;
            uint32_t bHi[4], bLo[4];
#pragma unroll
            for (int nj = 0; nj < 4; ++nj) {
                const uint32_t ro = SWZ((uint32_t)((nj * 16 + b_row) * 128 + kbb + b_khalf));
                ldmx4(bHi, stage + ro);
                ldmx4(bLo, stage + 8192 + ro);
                mma16816(sacc[2 * nj],     qHi[kb], &bHi[0]);
                mma16816(sacc[2 * nj + 1], qHi[kb], &bHi[2]);
                mma16816(sacc[2 * nj],     qLo[kb], &bHi[0]);
                mma16816(sacc[2 * nj + 1], qLo[kb], &bHi[2]);
                mma16816(sacc[2 * nj],     qHi[kb], &bLo[0]);
                mma16816(sacc[2 * nj + 1], qHi[kb], &bLo[2]);
            }
        }

        // ---- scale + causal mask ----
        if (kt >= 2 * qi) {
            const int colB = kt * 64;
#pragma unroll
            for (int ni = 0; ni < 8; ++ni) {
#pragma unroll
                for (int r = 0; r < 4; ++r) {
                    const int row = (r < 2) ? rowG0 : rowG1;
                    const int col = colB + ni * 8 + tc2 + (r & 1);
                    sacc[ni][r] = (col > row) ? -INFINITY : sacc[ni][r] * 0.125f;
                }
            }
        } else {
#pragma unroll
            for (int ni = 0; ni < 8; ++ni)
#pragma unroll
                for (int r = 0; r < 4; ++r) sacc[ni][r] *= 0.125f;
        }

        // ---- row max ----
        float mx0 = -INFINITY, mx1 = -INFINITY;
#pragma unroll
        for (int ni = 0; ni < 8; ++ni) {
            mx0 = fmaxf(mx0, fmaxf(sacc[ni][0], sacc[ni][1]));
            mx1 = fmaxf(mx1, fmaxf(sacc[ni][2], sacc[ni][3]));
        }
        mx0 = fmaxf(mx0, __shfl_xor_sync(0xffffffffu, mx0, 1));
        mx0 = fmaxf(mx0, __shfl_xor_sync(0xffffffffu, mx0, 2));
        mx1 = fmaxf(mx1, __shfl_xor_sync(0xffffffffu, mx1, 1));
        mx1 = fmaxf(mx1, __shfl_xor_sync(0xffffffffu, mx1, 2));

        const float mn0 = fmaxf(m0, mx0);
        const float mn1 = fmaxf(m1, mx1);
        const float c0 = __expf(m0 - mn0);
        const float c1 = __expf(m1 - mn1);
        m0 = mn0;  m1 = mn1;
#pragma unroll
        for (int ni = 0; ni < 8; ++ni) {
            o[ni][0] *= c0; o[ni][1] *= c0;
            o[ni][2] *= c1; o[ni][3] *= c1;
        }

        // ---- exp + register P fragments + O += P V (3-term) ----
        float rs0 = 0.f, rs1 = 0.f;
#pragma unroll
        for (int kb = 0; kb < 4; ++kb) {
            float e[8];
#pragma unroll
            for (int j = 0; j < 2; ++j) {
                const int ni = 2 * kb + j;
                e[4 * j + 0] = __expf(sacc[ni][0] - mn0);
                e[4 * j + 1] = __expf(sacc[ni][1] - mn0);
                e[4 * j + 2] = __expf(sacc[ni][2] - mn1);
                e[4 * j + 3] = __expf(sacc[ni][3] - mn1);
            }
            rs0 += e[0] + e[1] + e[4] + e[5];
            rs1 += e[2] + e[3] + e[6] + e[7];

            uint32_t pHi[4], pLo[4];
#pragma unroll
            for (int j = 0; j < 2; ++j) {
                const float p0 = e[4 * j + 0], p1 = e[4 * j + 1];
                const float p2 = e[4 * j + 2], p3 = e[4 * j + 3];
                const float h0 = __bfloat162float(__float2bfloat16(p0));
                const float h1 = __bfloat162float(__float2bfloat16(p1));
                const float h2 = __bfloat162float(__float2bfloat16(p2));
                const float h3 = __bfloat162float(__float2bfloat16(p3));
                pHi[2 * j + 0] = packbf2(h0, h1);
                pHi[2 * j + 1] = packbf2(h2, h3);
                pLo[2 * j + 0] = packbf2(p0 - h0, p1 - h1);
                pLo[2 * j + 1] = packbf2(p2 - h2, p3 - h3);
            }

            const int kbb = kb * 32;
            uint32_t vHi[4], vLo[4];
#pragma unroll
            for (int nj = 0; nj < 4; ++nj) {
                const uint32_t ro = SWZ((uint32_t)((nj * 16 + b_row) * 128 + kbb + b_khalf));
                ldmx4(vHi, stage + 16384 + ro);
                ldmx4(vLo, stage + 24576 + ro);
                mma16816(o[2 * nj],     pHi, &vHi[0]);
                mma16816(o[2 * nj + 1], pHi, &vHi[2]);
                mma16816(o[2 * nj],     pLo, &vHi[0]);
                mma16816(o[2 * nj + 1], pLo, &vHi[2]);
                mma16816(o[2 * nj],     pHi, &vLo[0]);
                mma16816(o[2 * nj + 1], pHi, &vLo[2]);
            }
        }

        rs0 += __shfl_xor_sync(0xffffffffu, rs0, 1);
        rs0 += __shfl_xor_sync(0xffffffffu, rs0, 2);
        rs1 += __shfl_xor_sync(0xffffffffu, rs1, 1);
        rs1 += __shfl_xor_sync(0xffffffffu, rs1, 2);
        l0 = l0 * c0 + rs0;
        l1 = l1 * c1 + rs1;

        if (++buf >= 3) buf = 0;
    }

    // ---- normalize + write split-bf16 [hi|lo|hi] proj input ----
    const float inv0 = 1.f / l0;
    const float inv1 = 1.f / l1;
    __nv_bfloat16* r0p = g_abig + (size_t)(b * SEQ + rowG0) * KEFF;
    __nv_bfloat16* r1p = g_abig + (size_t)(b * SEQ + rowG1) * KEFF;
#pragma unroll
    for (int ni = 0; ni < 8; ++ni) {
        const int c = h * HDIM + ni * 8 + tc2;
        {
            const float p0 = o[ni][0] * inv0;
            const float p1 = o[ni][1] * inv0;
            const __nv_bfloat16 h0 = __float2bfloat16(p0);
            const __nv_bfloat16 h1 = __float2bfloat16(p1);
            const __nv_bfloat16 l0b = __float2bfloat16(p0 - __bfloat162float(h0));
            const __nv_bfloat16 l1b = __float2bfloat16(p1 - __bfloat162float(h1));
            *(__nv_bfloat162*)(r0p + c)            = __nv_bfloat162(h0, h1);
            *(__nv_bfloat162*)(r0p + CDIM + c)     = __nv_bfloat162(l0b, l1b);
            *(__nv_bfloat162*)(r0p + 2 * CDIM + c) = __nv_bfloat162(h0, h1);
        }
        {
            const float p0 = o[ni][2] * inv1;
            const float p1 = o[ni][3] * inv1;
            const __nv_bfloat16 h0 = __float2bfloat16(p0);
            const __nv_bfloat16 h1 = __float2bfloat16(p1);
            const __nv_bfloat16 l0b = __float2bfloat16(p0 - __bfloat162float(h0));
            const __nv_bfloat16 l1b = __float2bfloat16(p1 - __bfloat162float(h1));
            *(__nv_bfloat162*)(r1p + c)            = __nv_bfloat162(h0, h1);
            *(__nv_bfloat162*)(r1p + CDIM + c)     = __nv_bfloat162(l0b, l1b);
            *(__nv_bfloat162*)(r1p + 2 * CDIM + c) = __nv_bfloat162(h0, h1);
        }
    }
}

// ---------------------------------------------------------------------------
// launch
// ---------------------------------------------------------------------------
extern "C" void kernel_launch(void* const* d_in, const int* in_sizes, int n_in,
                              void* d_out, int out_size)
{
    const float* x      = (const float*)d_in[0];
    const float* w_qkv  = (const float*)d_in[1];
    const float* b_qkv  = (const float*)d_in[2];
    const float* w_proj = (const float*)d_in[3];
    const float* b_proj = (const float*)d_in[4];
    float* out = (float*)d_out;

    __nv_bfloat16* abig = nullptr; __nv_bfloat16* wqkvt = nullptr; __nv_bfloat16* wprojt = nullptr;
    float* v32 = nullptr;
    cudaGetSymbolAddress((void**)&abig,   g_abig);
    cudaGetSymbolAddress((void**)&wqkvt,  g_wqkvt);
    cudaGetSymbolAddress((void**)&wprojt, g_wprojt);
    cudaGetSymbolAddress((void**)&v32,    g_v32);

    cudaFuncSetAttribute(gemm_mma_kernel,
                         cudaFuncAttributeMaxDynamicSharedMemorySize, GEMM_DYN_SMEM);
    cudaFuncSetAttribute(attention_tc_kernel,
                         cudaFuncAttributeMaxDynamicSharedMemorySize, ATT3_SMEM);

    // weight prep
    conv_wt_kernel<<<dim3(C3 / 32, CDIM / 32), dim3(32, 32)>>>(w_qkv, wqkvt, C3);
    conv_wt_kernel<<<dim3(CDIM / 32, CDIM / 32), dim3(32, 32)>>>(w_proj, wprojt, CDIM);

    // 1) qkv gemm (persistent, grid=296 for 768 tiles):
    //    writes split Q/K (g_q,g_k) + fp32 V (g_v32) directly
    conv_split_kernel<<<(MROWS * CDIM) / 256, 256>>>(x, abig);
    gemm_mma_kernel<<<296, 256, GEMM_DYN_SMEM>>>(
        abig, wqkvt, b_qkv, v32, C3, 1, (C3 / 128) * (MROWS / 128));

    // 2) V transpose+split prep
    prep_vt_kernel<<<dim3(SEQ / 32, HDIM / 32, NBH), dim3(32, 32)>>>();

    // 3) tensor-core flash attention -> writes split-bf16 into g_abig
    attention_tc_kernel<<<dim3(SEQ / 128, NBH), 256, ATT3_SMEM>>>();

    // 4) out = att @ w_proj + b_proj (256 tiles = one wave; loop degenerates)
    gemm_mma_kernel<<<256, 256, GEMM_DYN_SMEM>>>(
        abig, wprojt, b_proj, out, CDIM, 0, (CDIM / 128) * (MROWS / 128));
}

// round 12
// speedup vs baseline: 1.0362x; 1.0362x over previous
#include <cuda_runtime.h>
#include <cuda_bf16.h>
#include <math.h>
#include <stdint.h>

// Problem constants
#define BATCH   2
#define SEQ     2048
#define CDIM    1024
#define NHEAD   16
#define HDIM    64
#define C3      3072
#define MROWS   4096            // BATCH*SEQ
#define KEFF    3072            // split-bf16 effective K (= 3*CDIM)
#define NCHUNK  48              // KEFF / 64
#define NBH     32              // BATCH*NHEAD

// Scratch (device globals — no runtime allocation allowed)
__device__ float g_v32[MROWS * CDIM];                  // V (fp32) from QKV gemm
__device__ __nv_bfloat16 g_abig[MROWS * KEFF];         // split A: [hi | lo | hi]
__device__ __nv_bfloat16 g_wqkvt[C3 * KEFF];           // W_qkv^T split: [hi | hi | lo]
__device__ __nv_bfloat16 g_wprojt[CDIM * KEFF];        // W_proj^T split: [hi | hi | lo]
// per-head split attention operands
__device__ __nv_bfloat16 g_q[NBH * 2 * SEQ * HDIM];    // [bh][hi/lo][t][d]
__device__ __nv_bfloat16 g_k[NBH * 2 * SEQ * HDIM];    // [bh][hi/lo][t][d]
__device__ __nv_bfloat16 g_vt[NBH * 2 * HDIM * SEQ];   // [bh][hi/lo][d][t]

// ---------------------------------------------------------------------------
// Helpers (base-sm_100-legal PTX only)
// ---------------------------------------------------------------------------
__device__ __forceinline__ uint32_t smem_u32(const void* p) {
    uint32_t a;
    asm("{ .reg .u64 t; cvta.to.shared.u64 t, %1; cvt.u32.u64 %0, t; }" : "=r"(a) : "l"(p));
    return a;
}
__device__ __forceinline__ void cp_async16(uint32_t dst, const void* src) {
    asm volatile("cp.async.cg.shared.global [%0], [%1], 16;" :: "r"(dst), "l"(src));
}
#define CP_COMMIT()  asm volatile("cp.async.commit_group;")
#define CP_WAIT(n)   asm volatile("cp.async.wait_group %0;" :: "n"(n))

__device__ __forceinline__ void ldmx4(uint32_t* r, uint32_t addr) {
    asm volatile("ldmatrix.sync.aligned.m8n8.x4.shared.b16 {%0,%1,%2,%3}, [%4];"
                 : "=r"(r[0]), "=r"(r[1]), "=r"(r[2]), "=r"(r[3]) : "r"(addr));
}
__device__ __forceinline__ void mma16816(float* d, const uint32_t* a, const uint32_t* b) {
    asm volatile("mma.sync.aligned.m16n8k16.row.col.f32.bf16.bf16.f32 "
                 "{%0,%1,%2,%3}, {%4,%5,%6,%7}, {%8,%9}, {%0,%1,%2,%3};"
                 : "+f"(d[0]), "+f"(d[1]), "+f"(d[2]), "+f"(d[3])
                 : "r"(a[0]), "r"(a[1]), "r"(a[2]), "r"(a[3]), "r"(b[0]), "r"(b[1]));
}
__device__ __forceinline__ uint32_t packbf2(float x, float y) {
    const __nv_bfloat162 v = __floats2bfloat162_rn(x, y);   // x -> low half
    return *(const uint32_t*)&v;
}
#define SWZ(o) ((o) ^ (((o) >> 3) & 0x70))

// ---------------------------------------------------------------------------
// Merged input prep (one launch):
//  blocks [0, 3072):    W_qkv^T split  -> g_wqkvt [hi|hi|lo]
//  blocks [3072, 4096): W_proj^T split -> g_wprojt [hi|hi|lo]
//  blocks [4096, 8192): x split        -> g_abig  [hi|lo|hi]
// Block = 32x32 threads.
// ---------------------------------------------------------------------------
__global__ void __launch_bounds__(1024)
prep_all_kernel(const float* __restrict__ x,
                const float* __restrict__ w_qkv,
                const float* __restrict__ w_proj)
{
    const int tx = threadIdx.x;
    const int ty = threadIdx.y;
    const int bid = blockIdx.x;

    if (bid < 4096) {
        __shared__ float tile[32][33];
        const float* w;
        __nv_bfloat16* outp;
        int Nw, tb;
        if (bid < 3072) { w = w_qkv;  outp = g_wqkvt;  Nw = C3;   tb = bid; }
        else            { w = w_proj; outp = g_wprojt; Nw = CDIM; tb = bid - 3072; }
        const int ncolt = Nw >> 5;
        const int n0 = (tb % ncolt) * 32;
        const int k0 = (tb / ncolt) * 32;
        tile[ty][tx] = w[(size_t)(k0 + ty) * Nw + n0 + tx];
        __syncthreads();
        const int n = n0 + ty;
        const int k = k0 + tx;
        const float a = tile[tx][ty];
        const __nv_bfloat16 hi = __float2bfloat16(a);
        const __nv_bfloat16 lo = __float2bfloat16(a - __bfloat162float(hi));
        __nv_bfloat16* row = outp + (size_t)n * KEFF;
        row[k]            = hi;
        row[CDIM + k]     = hi;
        row[2 * CDIM + k] = lo;
    } else {
        const int idx = (bid - 4096) * 1024 + ty * 32 + tx;   // over MROWS*CDIM
        const int m = idx >> 10;
        const int k = idx & 1023;
        const float a = x[idx];
        const __nv_bfloat16 hi = __float2bfloat16(a);
        const __nv_bfloat16 lo = __float2bfloat16(a - __bfloat162float(hi));
        __nv_bfloat16* row = g_abig + (size_t)m * KEFF;
        row[k]            = hi;
        row[CDIM + k]     = lo;
        row[2 * CDIM + k] = hi;
    }
}

// ---------------------------------------------------------------------------
// Attention prep: transposed split V   g_vt[bh][seg][d][t]   (reads g_v32)
// ---------------------------------------------------------------------------
__global__ void __launch_bounds__(1024)
prep_vt_kernel()
{
    __shared__ float tile[32][33];
    const int bh = blockIdx.z;
    const int b  = bh >> 4;
    const int h  = bh & 15;
    const int t0 = blockIdx.x * 32;
    const int d0 = blockIdx.y * 32;

    tile[threadIdx.y][threadIdx.x] =
        g_v32[(size_t)(b * SEQ + t0 + threadIdx.y) * CDIM + h * HDIM + d0 + threadIdx.x];
    __syncthreads();
    const int d = d0 + threadIdx.y;
    const int t = t0 + threadIdx.x;
    const float v = tile[threadIdx.x][threadIdx.y];
    const __nv_bfloat16 hi = __float2bfloat16(v);
    const __nv_bfloat16 lo = __float2bfloat16(v - __bfloat162float(hi));
    g_vt[((size_t)(bh * 2 + 0) * HDIM + d) * SEQ + t] = hi;
    g_vt[((size_t)(bh * 2 + 1) * HDIM + d) * SEQ + t] = lo;
}

// ---------------------------------------------------------------------------
// Tensor-core bf16 GEMM (R8-exact, known 217us/72us):
// 3-stage cp.async pipeline, 1 sync per chunk. KEFF=3072 [hi|lo|hi]x[hi|hi|lo].
// mode 0: out = A*Bt + bias (fp32). mode 1: QKV epilogue split writes.
// ---------------------------------------------------------------------------
#define GEMM_DYN_SMEM (3 * 32768)

__global__ void __launch_bounds__(256, 2)
gemm_mma_kernel(const __nv_bfloat16* __restrict__ A, const __nv_bfloat16* __restrict__ Bt,
                const float* __restrict__ bias, float* __restrict__ out, int Nout, int mode)
{
    extern __shared__ __align__(1024) char dyn[];
    const uint32_t tiles = smem_u32(dyn);

    const int tid = threadIdx.x;
    const int wid = tid >> 5;
    const int lane = tid & 31;
    const int wm = wid & 1;
    const int wn = wid >> 1;
    const int m0 = blockIdx.y * 128;
    const int n0 = blockIdx.x * 128;

    const __nv_bfloat16* Arow = A  + (size_t)m0 * KEFF;
    const __nv_bfloat16* Brow = Bt + (size_t)n0 * KEFF;

    auto load_chunk = [&](int c, int buf) {
        const uint32_t abase = tiles + buf * 32768;
        const uint32_t bbase = abase + 16384;
        const __nv_bfloat16* ag = Arow + c * 64;
        const __nv_bfloat16* bg = Brow + c * 64;
#pragma unroll
        for (int i = 0; i < 4; ++i) {
            const int g   = tid + 256 * i;
            const int row = g >> 3;
            const int gc  = g & 7;
            const uint32_t off = SWZ((uint32_t)(row * 128 + gc * 16));
            cp_async16(abase + off, (const char*)(ag + (size_t)row * KEFF) + gc * 16);
            cp_async16(bbase + off, (const char*)(bg + (size_t)row * KEFF) + gc * 16);
        }
        CP_COMMIT();
    };

    float acc[4][4][4];
#pragma unroll
    for (int mi = 0; mi < 4; ++mi)
#pragma unroll
        for (int ni = 0; ni < 4; ++ni)
#pragma unroll
            for (int r = 0; r < 4; ++r) acc[mi][ni][r] = 0.f;

    const int l15 = lane & 15;
    const int lhi16 = (lane >> 4) * 16;
    const int b_row = ((lane & 16) >> 1) + (lane & 7);
    const int b_khalf = (lane & 8) ? 16 : 0;

    load_chunk(0, 0);
    load_chunk(1, 1);

    int buf = 0;
    for (int c = 0; c < NCHUNK; ++c) {
        if (c < NCHUNK - 1) { CP_WAIT(1); } else { CP_WAIT(0); }
        __syncthreads();
        if (c + 2 < NCHUNK) {
            int nb = buf + 2; if (nb >= 3) nb -= 3;
            load_chunk(c + 2, nb);
        }

        const uint32_t abase = tiles + buf * 32768;
        const uint32_t bbase = abase + 16384;

#pragma unroll
        for (int ks = 0; ks < 4; ++ks) {
            const int kb = ks * 32;
            uint32_t afr[4][4];
#pragma unroll
            for (int mi = 0; mi < 4; ++mi) {
                const int row = wm * 64 + mi * 16 + l15;
                ldmx4(afr[mi], abase + SWZ((uint32_t)(row * 128 + kb + lhi16)));
            }
            uint32_t bfr[2][4];
#pragma unroll
            for (int nj = 0; nj < 2; ++nj) {
                const int row = wn * 32 + nj * 16 + b_row;
                ldmx4(bfr[nj], bbase + SWZ((uint32_t)(row * 128 + kb + b_khalf)));
            }
#pragma unroll
            for (int mi = 0; mi < 4; ++mi) {
#pragma unroll
                for (int ni = 0; ni < 4; ++ni)
                    mma16816(acc[mi][ni], afr[mi], &bfr[ni >> 1][(ni & 1) * 2]);
            }
        }
        if (++buf >= 3) buf = 0;
    }

    const int tr = lane >> 2;
    const int tc = (lane & 3) * 2;

    auto wsplit = [&](__nv_bfloat16* basep, int gr_, int cc, float a0, float a1) {
        const int t  = gr_ & (SEQ - 1);
        const int bb = gr_ >> 11;
        const int hh = cc >> 6;
        const int dd = cc & 63;
        const int bhx = bb * NHEAD + hh;
        const __nv_bfloat16 h0 = __float2bfloat16(a0);
        const __nv_bfloat16 h1 = __float2bfloat16(a1);
        const __nv_bfloat16 l0 = __float2bfloat16(a0 - __bfloat162float(h0));
        const __nv_bfloat16 l1 = __float2bfloat16(a1 - __bfloat162float(h1));
        *(__nv_bfloat162*)(basep + ((size_t)(bhx * 2 + 0) * SEQ + t) * HDIM + dd) = __nv_bfloat162(h0, h1);
        *(__nv_bfloat162*)(basep + ((size_t)(bhx * 2 + 1) * SEQ + t) * HDIM + dd) = __nv_bfloat162(l0, l1);
    };

#pragma unroll
    for (int mi = 0; mi < 4; ++mi) {
#pragma unroll
        for (int ni = 0; ni < 4; ++ni) {
            const int gr = m0 + wm * 64 + mi * 16 + tr;
            const int gc = n0 + wn * 32 + ni * 8 + tc;
            const float b0 = bias[gc], b1 = bias[gc + 1];
            const float y00 = acc[mi][ni][0] + b0, y01 = acc[mi][ni][1] + b1;
            const float y10 = acc[mi][ni][2] + b0, y11 = acc[mi][ni][3] + b1;
            if (mode == 0) {
                *(float2*)(out + (size_t)gr * Nout + gc)       = make_float2(y00, y01);
                *(float2*)(out + (size_t)(gr + 8) * Nout + gc) = make_float2(y10, y11);
            } else {
                if (gc < CDIM) {
                    wsplit(g_q, gr, gc, y00, y01);
                    wsplit(g_q, gr + 8, gc, y10, y11);
                } else if (gc < 2 * CDIM) {
                    wsplit(g_k, gr, gc - CDIM, y00, y01);
                    wsplit(g_k, gr + 8, gc - CDIM, y10, y11);
                } else {
                    const int cc = gc - 2 * CDIM;
                    *(float2*)(g_v32 + (size_t)gr * CDIM + cc)       = make_float2(y00, y01);
                    *(float2*)(g_v32 + (size_t)(gr + 8) * CDIM + cc) = make_float2(y10, y11);
                }
            }
        }
    }
}

// ---------------------------------------------------------------------------
// Tensor-core flash attention (R8-exact):
// Q-tile 128, 8 warps x 16 rows; Q fragments register-resident; P converted
// to bf16 hi/lo in registers and fed directly as mma A operand.
// 3-stage KV pipeline, 1 sync per kt. No reg cap (no min-blocks).
// ---------------------------------------------------------------------------
#define ATT3_SMEM (3 * 32768)

__global__ void __launch_bounds__(256)
attention_tc_kernel()
{
    extern __shared__ __align__(1024) char dyn[];
    const uint32_t sb = smem_u32(dyn);
    const int tid  = threadIdx.x;
    const int wid  = tid >> 5;
    const int lane = tid & 31;

    const int qi = gridDim.x - 1 - blockIdx.x;   // heavy tiles first
    const int bh = blockIdx.y;
    const int b  = bh >> 4;
    const int h  = bh & 15;

    const int l15 = lane & 15;
    const int lhi16 = (lane >> 4) * 16;
    const int b_row = ((lane & 16) >> 1) + (lane & 7);
    const int b_khalf = (lane & 8) ? 16 : 0;
    const int tr = lane >> 2;
    const int tc2 = (lane & 3) * 2;

    // ---- stage Q (hi/lo): 2 segs x 128 rows x 128B into stage0/1 ----
#pragma unroll
    for (int i = 0; i < 8; ++i) {
        const int g = tid + 256 * i;          // 0..2047
        const int seg = g >> 10;
        const int r   = (g >> 3) & 127;
        const int gc  = g & 7;
        const uint32_t dst = sb + seg * 16384 + SWZ((uint32_t)(r * 128 + gc * 16));
        const char* src = (const char*)&g_q[((size_t)(bh * 2 + seg) * SEQ + qi * 128 + r) * HDIM] + gc * 16;
        cp_async16(dst, src);
    }
    CP_COMMIT(); CP_WAIT(0);
    __syncthreads();

    // ---- Q fragments into registers (warp owns rows 16*wid..16*wid+15) ----
    uint32_t qHi[4][4], qLo[4][4];
#pragma unroll
    for (int kb = 0; kb < 4; ++kb) {
        const uint32_t off = SWZ((uint32_t)((16 * wid + l15) * 128 + kb * 32 + lhi16));
        ldmx4(qHi[kb], sb + off);
        ldmx4(qLo[kb], sb + 16384 + off);
    }
    __syncthreads();   // everyone done reading stage0/1 before KV overwrites

    // KV stage loader
    auto load_kv = [&](int kt, int buf) {
        const uint32_t stage = sb + buf * 32768;
#pragma unroll
        for (int i = 0; i < 8; ++i) {
            const int g = tid + 256 * i;      // 0..2047
            const int half = g >> 10;         // 0=K, 1=Vt
            const int seg  = (g >> 9) & 1;
            const int r    = (g >> 3) & 63;
            const int gc   = g & 7;
            const uint32_t dst = stage + half * 16384 + seg * 8192 + SWZ((uint32_t)(r * 128 + gc * 16));
            const char* src = (half == 0)
                ? (const char*)&g_k[((size_t)(bh * 2 + seg) * SEQ + kt * 64 + r) * HDIM] + gc * 16
                : (const char*)&g_vt[((size_t)(bh * 2 + seg) * HDIM + r) * SEQ + kt * 64] + gc * 16;
            cp_async16(dst, src);
        }
        CP_COMMIT();
    };

    const int last = 2 * qi + 1;
    load_kv(0, 0);
    load_kv(1, 1);

    float o[8][4];
#pragma unroll
    for (int ni = 0; ni < 8; ++ni)
#pragma unroll
        for (int r = 0; r < 4; ++r) o[ni][r] = 0.f;
    float m0 = -INFINITY, m1 = -INFINITY;
    float l0 = 0.f, l1 = 0.f;

    const int rowG0 = qi * 128 + 16 * wid + tr;
    const int rowG1 = rowG0 + 8;

    int buf = 0;
    for (int kt = 0; kt <= last; ++kt) {
        if (kt < last) { CP_WAIT(1); } else { CP_WAIT(0); }
        __syncthreads();
        if (kt + 2 <= last) {
            int nb = buf + 2; if (nb >= 3) nb -= 3;
            load_kv(kt + 2, nb);
        }
        const uint32_t stage = sb + buf * 32768;

        // ---- S = Q K^T (3-term split) ----
        float sacc[8][4];
#pragma unroll
        for (int ni = 0; ni < 8; ++ni)
#pragma unroll
            for (int r = 0; r < 4; ++r) sacc[ni][r] = 0.f;

#pragma unroll
        for (int kb = 0; kb < 4; ++kb) {
            const int kbb = kb * 32;
            uint32_t bHi[4], bLo[4];
#pragma unroll
            for (int nj = 0; nj < 4; ++nj) {
                const uint32_t ro = SWZ((uint32_t)((nj * 16 + b_row) * 128 + kbb + b_khalf));
                ldmx4(bHi, stage + ro);
                ldmx4(bLo, stage + 8192 + ro);
                mma16816(sacc[2 * nj],     qHi[kb], &bHi[0]);
                mma16816(sacc[2 * nj + 1], qHi[kb], &bHi[2]);
                mma16816(sacc[2 * nj],     qLo[kb], &bHi[0]);
                mma16816(sacc[2 * nj + 1], qLo[kb], &bHi[2]);
                mma16816(sacc[2 * nj],     qHi[kb], &bLo[0]);
                mma16816(sacc[2 * nj + 1], qHi[kb], &bLo[2]);
            }
        }

        // ---- scale + causal mask ----
        if (kt >= 2 * qi) {
            const int colB = kt * 64;
#pragma unroll
            for (int ni = 0; ni < 8; ++ni) {
#pragma unroll
                for (int r = 0; r < 4; ++r) {
                    const int row = (r < 2) ? rowG0 : rowG1;
                    const int col = colB + ni * 8 + tc2 + (r & 1);
                    sacc[ni][r] = (col > row) ? -INFINITY : sacc[ni][r] * 0.125f;
                }
            }
        } else {
#pragma unroll
            for (int ni = 0; ni < 8; ++ni)
#pragma unroll
                for (int r = 0; r < 4; ++r) sacc[ni][r] *= 0.125f;
        }

        // ---- row max ----
        float mx0 = -INFINITY, mx1 = -INFINITY;
#pragma unroll
        for (int ni = 0; ni < 8; ++ni) {
            mx0 = fmaxf(mx0, fmaxf(sacc[ni][0], sacc[ni][1]));
            mx1 = fmaxf(mx1, fmaxf(sacc[ni][2], sacc[ni][3]));
        }
        mx0 = fmaxf(mx0, __shfl_xor_sync(0xffffffffu, mx0, 1));
        mx0 = fmaxf(mx0, __shfl_xor_sync(0xffffffffu, mx0, 2));
        mx1 = fmaxf(mx1, __shfl_xor_sync(0xffffffffu, mx1, 1));
        mx1 = fmaxf(mx1, __shfl_xor_sync(0xffffffffu, mx1, 2));

        const float mn0 = fmaxf(m0, mx0);
        const float mn1 = fmaxf(m1, mx1);
        const float c0 = __expf(m0 - mn0);
        const float c1 = __expf(m1 - mn1);
        m0 = mn0;  m1 = mn1;
#pragma unroll
        for (int ni = 0; ni < 8; ++ni) {
            o[ni][0] *= c0; o[ni][1] *= c0;
            o[ni][2] *= c1; o[ni][3] *= c1;
        }

        // ---- exp + register P fragments + O += P V (3-term) ----
        float rs0 = 0.f, rs1 = 0.f;
#pragma unroll
        for (int kb = 0; kb < 4; ++kb) {
            float e[8];
#pragma unroll
            for (int j = 0; j < 2; ++j) {
                const int ni = 2 * kb + j;
                e[4 * j + 0] = __expf(sacc[ni][0] - mn0);
                e[4 * j + 1] = __expf(sacc[ni][1] - mn0);
                e[4 * j + 2] = __expf(sacc[ni][2] - mn1);
                e[4 * j + 3] = __expf(sacc[ni][3] - mn1);
            }
            rs0 += e[0] + e[1] + e[4] + e[5];
            rs1 += e[2] + e[3] + e[6] + e[7];

            uint32_t pHi[4], pLo[4];
#pragma unroll
            for (int j = 0; j < 2; ++j) {
                const float p0 = e[4 * j + 0], p1 = e[4 * j + 1];
                const float p2 = e[4 * j + 2], p3 = e[4 * j + 3];
                const float h0 = __bfloat162float(__float2bfloat16(p0));
                const float h1 = __bfloat162float(__float2bfloat16(p1));
                const float h2 = __bfloat162float(__float2bfloat16(p2));
                const float h3 = __bfloat162float(__float2bfloat16(p3));
                pHi[2 * j + 0] = packbf2(h0, h1);
                pHi[2 * j + 1] = packbf2(h2, h3);
                pLo[2 * j + 0] = packbf2(p0 - h0, p1 - h1);
                pLo[2 * j + 1] = packbf2(p2 - h2, p3 - h3);
            }

            const int kbb = kb * 32;
            uint32_t vHi[4], vLo[4];
#pragma unroll
            for (int nj = 0; nj < 4; ++nj) {
                const uint32_t ro = SWZ((uint32_t)((nj * 16 + b_row) * 128 + kbb + b_khalf));
                ldmx4(vHi, stage + 16384 + ro);
                ldmx4(vLo, stage + 24576 + ro);
                mma16816(o[2 * nj],     pHi, &vHi[0]);
                mma16816(o[2 * nj + 1], pHi, &vHi[2]);
                mma16816(o[2 * nj],     pLo, &vHi[0]);
                mma16816(o[2 * nj + 1], pLo, &vHi[2]);
                mma16816(o[2 * nj],     pHi, &vLo[0]);
                mma16816(o[2 * nj + 1], pHi, &vLo[2]);
            }
        }

        rs0 += __shfl_xor_sync(0xffffffffu, rs0, 1);
        rs0 += __shfl_xor_sync(0xffffffffu, rs0, 2);
        rs1 += __shfl_xor_sync(0xffffffffu, rs1, 1);
        rs1 += __shfl_xor_sync(0xffffffffu, rs1, 2);
        l0 = l0 * c0 + rs0;
        l1 = l1 * c1 + rs1;

        if (++buf >= 3) buf = 0;
    }

    // ---- normalize + write split-bf16 [hi|lo|hi] proj input ----
    const float inv0 = 1.f / l0;
    const float inv1 = 1.f / l1;
    __nv_bfloat16* r0p = g_abig + (size_t)(b * SEQ + rowG0) * KEFF;
    __nv_bfloat16* r1p = g_abig + (size_t)(b * SEQ + rowG1) * KEFF;
#pragma unroll
    for (int ni = 0; ni < 8; ++ni) {
        const int c = h * HDIM + ni * 8 + tc2;
        {
            const float p0 = o[ni][0] * inv0;
            const float p1 = o[ni][1] * inv0;
            const __nv_bfloat16 h0 = __float2bfloat16(p0);
            const __nv_bfloat16 h1 = __float2bfloat16(p1);
            const __nv_bfloat16 l0b = __float2bfloat16(p0 - __bfloat162float(h0));
            const __nv_bfloat16 l1b = __float2bfloat16(p1 - __bfloat162float(h1));
            *(__nv_bfloat162*)(r0p + c)            = __nv_bfloat162(h0, h1);
            *(__nv_bfloat162*)(r0p + CDIM + c)     = __nv_bfloat162(l0b, l1b);
            *(__nv_bfloat162*)(r0p + 2 * CDIM + c) = __nv_bfloat162(h0, h1);
        }
        {
            const float p0 = o[ni][2] * inv1;
            const float p1 = o[ni][3] * inv1;
            const __nv_bfloat16 h0 = __float2bfloat16(p0);
            const __nv_bfloat16 h1 = __float2bfloat16(p1);
            const __nv_bfloat16 l0b = __float2bfloat16(p0 - __bfloat162float(h0));
            const __nv_bfloat16 l1b = __float2bfloat16(p1 - __bfloat162float(h1));
            *(__nv_bfloat162*)(r1p + c)            = __nv_bfloat162(h0, h1);
            *(__nv_bfloat162*)(r1p + CDIM + c)     = __nv_bfloat162(l0b, l1b);
            *(__nv_bfloat162*)(r1p + 2 * CDIM + c) = __nv_bfloat162(h0, h1);
        }
    }
}

// ---------------------------------------------------------------------------
// launch
// ---------------------------------------------------------------------------
extern "C" void kernel_launch(void* const* d_in, const int* in_sizes, int n_in,
                              void* d_out, int out_size)
{
    const float* x      = (const float*)d_in[0];
    const float* w_qkv  = (const float*)d_in[1];
    const float* b_qkv  = (const float*)d_in[2];
    const float* w_proj = (const float*)d_in[3];
    const float* b_proj = (const float*)d_in[4];
    float* out = (float*)d_out;

    __nv_bfloat16* abig = nullptr; __nv_bfloat16* wqkvt = nullptr; __nv_bfloat16* wprojt = nullptr;
    float* v32 = nullptr;
    cudaGetSymbolAddress((void**)&abig,   g_abig);
    cudaGetSymbolAddress((void**)&wqkvt,  g_wqkvt);
    cudaGetSymbolAddress((void**)&wprojt, g_wprojt);
    cudaGetSymbolAddress((void**)&v32,    g_v32);

    cudaFuncSetAttribute(gemm_mma_kernel,
                         cudaFuncAttributeMaxDynamicSharedMemorySize, GEMM_DYN_SMEM);
    cudaFuncSetAttribute(attention_tc_kernel,
                         cudaFuncAttributeMaxDynamicSharedMemorySize, ATT3_SMEM);

    // 0) all input prep in one launch (weights transpose+split, x split)
    prep_all_kernel<<<8192, dim3(32, 32)>>>(x, w_qkv, w_proj);

    // 1) qkv gemm: writes split Q/K (g_q,g_k) + fp32 V (g_v32) directly
    gemm_mma_kernel<<<dim3(C3 / 128, MROWS / 128), 256, GEMM_DYN_SMEM>>>(
        abig, wqkvt, b_qkv, v32, C3, 1);

    // 2) V transpose+split prep
    prep_vt_kernel<<<dim3(SEQ / 32, HDIM / 32, NBH), dim3(32, 32)>>>();

    // 3) tensor-core flash attention -> writes split-bf16 into g_abig
    attention_tc_kernel<<<dim3(SEQ / 128, NBH), 256, ATT3_SMEM>>>();

    // 4) out = att @ w_proj + b_proj
    gemm_mma_kernel<<<dim3(CDIM / 128, MROWS / 128), 256, GEMM_DYN_SMEM>>>(
        abig, wprojt, b_proj, out, CDIM, 0);
}

// round 13
// speedup vs baseline: 1.0843x; 1.0464x over previous
#include <cuda_runtime.h>
#include <cuda_bf16.h>
#include <math.h>
#include <stdint.h>

// Problem constants
#define BATCH   2
#define SEQ     2048
#define CDIM    1024
#define NHEAD   16
#define HDIM    64
#define C3      3072
#define MROWS   4096            // BATCH*SEQ
#define KEFF    3072            // split-bf16 effective K (= 3*CDIM)
#define NCHUNK  48              // KEFF / 64
#define NBH     32              // BATCH*NHEAD

// Scratch (device globals — no runtime allocation allowed)
__device__ __nv_bfloat16 g_abig[MROWS * KEFF];         // split A: [hi | lo | hi]
__device__ __nv_bfloat16 g_wqkvt[C3 * KEFF];           // W_qkv^T split: [hi | hi | lo]
__device__ __nv_bfloat16 g_wprojt[CDIM * KEFF];        // W_proj^T split: [hi | hi | lo]
// per-head split attention operands
__device__ __nv_bfloat16 g_q[NBH * 2 * SEQ * HDIM];    // [bh][hi/lo][t][d]
__device__ __nv_bfloat16 g_k[NBH * 2 * SEQ * HDIM];    // [bh][hi/lo][t][d]
__device__ __nv_bfloat16 g_vt[NBH * 2 * HDIM * SEQ];   // [bh][hi/lo][d][t]

// ---------------------------------------------------------------------------
// Helpers (base-sm_100-legal PTX only)
// ---------------------------------------------------------------------------
__device__ __forceinline__ uint32_t smem_u32(const void* p) {
    uint32_t a;
    asm("{ .reg .u64 t; cvta.to.shared.u64 t, %1; cvt.u32.u64 %0, t; }" : "=r"(a) : "l"(p));
    return a;
}
__device__ __forceinline__ void cp_async16(uint32_t dst, const void* src) {
    asm volatile("cp.async.cg.shared.global [%0], [%1], 16;" :: "r"(dst), "l"(src));
}
#define CP_COMMIT()  asm volatile("cp.async.commit_group;")
#define CP_WAIT(n)   asm volatile("cp.async.wait_group %0;" :: "n"(n))

__device__ __forceinline__ void ldmx4(uint32_t* r, uint32_t addr) {
    asm volatile("ldmatrix.sync.aligned.m8n8.x4.shared.b16 {%0,%1,%2,%3}, [%4];"
                 : "=r"(r[0]), "=r"(r[1]), "=r"(r[2]), "=r"(r[3]) : "r"(addr));
}
__device__ __forceinline__ void mma16816(float* d, const uint32_t* a, const uint32_t* b) {
    asm volatile("mma.sync.aligned.m16n8k16.row.col.f32.bf16.bf16.f32 "
                 "{%0,%1,%2,%3}, {%4,%5,%6,%7}, {%8,%9}, {%0,%1,%2,%3};"
                 : "+f"(d[0]), "+f"(d[1]), "+f"(d[2]), "+f"(d[3])
                 : "r"(a[0]), "r"(a[1]), "r"(a[2]), "r"(a[3]), "r"(b[0]), "r"(b[1]));
}
__device__ __forceinline__ uint32_t packbf2(float x, float y) {
    const __nv_bfloat162 v = __floats2bfloat162_rn(x, y);   // x -> low half
    return *(const uint32_t*)&v;
}
__device__ __forceinline__ float ex2f(float x) {
    float y;
    asm("ex2.approx.ftz.f32 %0, %1;" : "=f"(y) : "f"(x));
    return y;
}
#define SWZ(o) ((o) ^ (((o) >> 3) & 0x70))

// scale folded with log2(e): softmax done in base-2 domain
#define SCALE2 0.1803368752f    // 0.125 * 1.4426950408889634

// ---------------------------------------------------------------------------
// Merged input prep (one launch):
//  blocks [0, 3072):    W_qkv^T split  -> g_wqkvt [hi|hi|lo]
//  blocks [3072, 4096): W_proj^T split -> g_wprojt [hi|hi|lo]
//  blocks [4096, 8192): x split        -> g_abig  [hi|lo|hi]
// ---------------------------------------------------------------------------
__global__ void __launch_bounds__(1024)
prep_all_kernel(const float* __restrict__ x,
                const float* __restrict__ w_qkv,
                const float* __restrict__ w_proj)
{
    const int tx = threadIdx.x;
    const int ty = threadIdx.y;
    const int bid = blockIdx.x;

    if (bid < 4096) {
        __shared__ float tile[32][33];
        const float* w;
        __nv_bfloat16* outp;
        int Nw, tb;
        if (bid < 3072) { w = w_qkv;  outp = g_wqkvt;  Nw = C3;   tb = bid; }
        else            { w = w_proj; outp = g_wprojt; Nw = CDIM; tb = bid - 3072; }
        const int ncolt = Nw >> 5;
        const int n0 = (tb % ncolt) * 32;
        const int k0 = (tb / ncolt) * 32;
        tile[ty][tx] = w[(size_t)(k0 + ty) * Nw + n0 + tx];
        __syncthreads();
        const int n = n0 + ty;
        const int k = k0 + tx;
        const float a = tile[tx][ty];
        const __nv_bfloat16 hi = __float2bfloat16(a);
        const __nv_bfloat16 lo = __float2bfloat16(a - __bfloat162float(hi));
        __nv_bfloat16* row = outp + (size_t)n * KEFF;
        row[k]            = hi;
        row[CDIM + k]     = hi;
        row[2 * CDIM + k] = lo;
    } else {
        const int idx = (bid - 4096) * 1024 + ty * 32 + tx;   // over MROWS*CDIM
        const int m = idx >> 10;
        const int k = idx & 1023;
        const float a = x[idx];
        const __nv_bfloat16 hi = __float2bfloat16(a);
        const __nv_bfloat16 lo = __float2bfloat16(a - __bfloat162float(hi));
        __nv_bfloat16* row = g_abig + (size_t)m * KEFF;
        row[k]            = hi;
        row[CDIM + k]     = lo;
        row[2 * CDIM + k] = hi;
    }
}

// ---------------------------------------------------------------------------
// Tensor-core bf16 GEMM (R8-exact mainloop):
// 3-stage cp.async pipeline, 1 sync per chunk. KEFF=3072 [hi|lo|hi]x[hi|hi|lo].
// mode 0: out = A*Bt + bias (fp32).
// mode 1: QKV epilogue — split Q/K to g_q/g_k; V transposed+split to g_vt.
// ---------------------------------------------------------------------------
#define GEMM_DYN_SMEM (3 * 32768)

__global__ void __launch_bounds__(256, 2)
gemm_mma_kernel(const __nv_bfloat16* __restrict__ A, const __nv_bfloat16* __restrict__ Bt,
                const float* __restrict__ bias, float* __restrict__ out, int Nout, int mode)
{
    extern __shared__ __align__(1024) char dyn[];
    const uint32_t tiles = smem_u32(dyn);

    const int tid = threadIdx.x;
    const int wid = tid >> 5;
    const int lane = tid & 31;
    const int wm = wid & 1;
    const int wn = wid >> 1;
    const int m0 = blockIdx.y * 128;
    const int n0 = blockIdx.x * 128;

    const __nv_bfloat16* Arow = A  + (size_t)m0 * KEFF;
    const __nv_bfloat16* Brow = Bt + (size_t)n0 * KEFF;

    auto load_chunk = [&](int c, int buf) {
        const uint32_t abase = tiles + buf * 32768;
        const uint32_t bbase = abase + 16384;
        const __nv_bfloat16* ag = Arow + c * 64;
        const __nv_bfloat16* bg = Brow + c * 64;
#pragma unroll
        for (int i = 0; i < 4; ++i) {
            const int g   = tid + 256 * i;
            const int row = g >> 3;
            const int gc  = g & 7;
            const uint32_t off = SWZ((uint32_t)(row * 128 + gc * 16));
            cp_async16(abase + off, (const char*)(ag + (size_t)row * KEFF) + gc * 16);
            cp_async16(bbase + off, (const char*)(bg + (size_t)row * KEFF) + gc * 16);
        }
        CP_COMMIT();
    };

    float acc[4][4][4];
#pragma unroll
    for (int mi = 0; mi < 4; ++mi)
#pragma unroll
        for (int ni = 0; ni < 4; ++ni)
#pragma unroll
            for (int r = 0; r < 4; ++r) acc[mi][ni][r] = 0.f;

    const int l15 = lane & 15;
    const int lhi16 = (lane >> 4) * 16;
    const int b_row = ((lane & 16) >> 1) + (lane & 7);
    const int b_khalf = (lane & 8) ? 16 : 0;

    load_chunk(0, 0);
    load_chunk(1, 1);

    int buf = 0;
    for (int c = 0; c < NCHUNK; ++c) {
        if (c < NCHUNK - 1) { CP_WAIT(1); } else { CP_WAIT(0); }
        __syncthreads();
        if (c + 2 < NCHUNK) {
            int nb = buf + 2; if (nb >= 3) nb -= 3;
            load_chunk(c + 2, nb);
        }

        const uint32_t abase = tiles + buf * 32768;
        const uint32_t bbase = abase + 16384;

#pragma unroll
        for (int ks = 0; ks < 4; ++ks) {
            const int kb = ks * 32;
            uint32_t afr[4][4];
#pragma unroll
            for (int mi = 0; mi < 4; ++mi) {
                const int row = wm * 64 + mi * 16 + l15;
                ldmx4(afr[mi], abase + SWZ((uint32_t)(row * 128 + kb + lhi16)));
            }
            uint32_t bfr[2][4];
#pragma unroll
            for (int nj = 0; nj < 2; ++nj) {
                const int row = wn * 32 + nj * 16 + b_row;
                ldmx4(bfr[nj], bbase + SWZ((uint32_t)(row * 128 + kb + b_khalf)));
            }
#pragma unroll
            for (int mi = 0; mi < 4; ++mi) {
#pragma unroll
                for (int ni = 0; ni < 4; ++ni)
                    mma16816(acc[mi][ni], afr[mi], &bfr[ni >> 1][(ni & 1) * 2]);
            }
        }
        if (++buf >= 3) buf = 0;
    }

    const int tr = lane >> 2;
    const int tc = (lane & 3) * 2;

    auto wsplit = [&](__nv_bfloat16* basep, int gr_, int cc, float a0, float a1) {
        const int t  = gr_ & (SEQ - 1);
        const int bb = gr_ >> 11;
        const int hh = cc >> 6;
        const int dd = cc & 63;
        const int bhx = bb * NHEAD + hh;
        const __nv_bfloat16 h0 = __float2bfloat16(a0);
        const __nv_bfloat16 h1 = __float2bfloat16(a1);
        const __nv_bfloat16 l0 = __float2bfloat16(a0 - __bfloat162float(h0));
        const __nv_bfloat16 l1 = __float2bfloat16(a1 - __bfloat162float(h1));
        *(__nv_bfloat162*)(basep + ((size_t)(bhx * 2 + 0) * SEQ + t) * HDIM + dd) = __nv_bfloat162(h0, h1);
        *(__nv_bfloat162*)(basep + ((size_t)(bhx * 2 + 1) * SEQ + t) * HDIM + dd) = __nv_bfloat162(l0, l1);
    };
    // V region: write transposed split directly into g_vt[bh][seg][d][t]
    auto wv = [&](int gr_, int cc, float a0, float a1) {
        const int t  = gr_ & (SEQ - 1);
        const int bb = gr_ >> 11;
        const int hh = cc >> 6;
        const int dd = cc & 63;
        const int bhx = bb * NHEAD + hh;
        const __nv_bfloat16 h0 = __float2bfloat16(a0);
        const __nv_bfloat16 h1 = __float2bfloat16(a1);
        const __nv_bfloat16 l0 = __float2bfloat16(a0 - __bfloat162float(h0));
        const __nv_bfloat16 l1 = __float2bfloat16(a1 - __bfloat162float(h1));
        const size_t bhi = ((size_t)(bhx * 2 + 0) * HDIM + dd) * SEQ + t;
        const size_t blo = ((size_t)(bhx * 2 + 1) * HDIM + dd) * SEQ + t;
        g_vt[bhi]       = h0;
        g_vt[bhi + SEQ] = h1;
        g_vt[blo]       = l0;
        g_vt[blo + SEQ] = l1;
    };

#pragma unroll
    for (int mi = 0; mi < 4; ++mi) {
#pragma unroll
        for (int ni = 0; ni < 4; ++ni) {
            const int gr = m0 + wm * 64 + mi * 16 + tr;
            const int gc = n0 + wn * 32 + ni * 8 + tc;
            const float b0 = bias[gc], b1 = bias[gc + 1];
            const float y00 = acc[mi][ni][0] + b0, y01 = acc[mi][ni][1] + b1;
            const float y10 = acc[mi][ni][2] + b0, y11 = acc[mi][ni][3] + b1;
            if (mode == 0) {
                *(float2*)(out + (size_t)gr * Nout + gc)       = make_float2(y00, y01);
                *(float2*)(out + (size_t)(gr + 8) * Nout + gc) = make_float2(y10, y11);
            } else {
                if (gc < CDIM) {
                    wsplit(g_q, gr, gc, y00, y01);
                    wsplit(g_q, gr + 8, gc, y10, y11);
                } else if (gc < 2 * CDIM) {
                    wsplit(g_k, gr, gc - CDIM, y00, y01);
                    wsplit(g_k, gr + 8, gc - CDIM, y10, y11);
                } else {
                    wv(gr, gc - 2 * CDIM, y00, y01);
                    wv(gr + 8, gc - 2 * CDIM, y10, y11);
                }
            }
        }
    }
}

// ---------------------------------------------------------------------------
// Tensor-core flash attention v4: 128-key KV tiles (halved per-iter overhead).
// Q-tile 128, 8 warps x 16 rows; Q fragments register-resident; P converted
// to bf16 hi/lo in registers and fed directly as mma A operand.
// 3-stage KV pipeline (64KB stages), 1 sync per 128 keys. exp2-domain softmax.
// smem: Qhi 16K @0, Qlo 16K @16K; stages @32K + buf*64K:
//       {Khi 16K (128 keys x 128B), Klo 16K, Vthi 2x8K blocks, Vtlo 2x8K}.
// ---------------------------------------------------------------------------
#define ATT5_SMEM (32768 + 3 * 65536)

__global__ void __launch_bounds__(256)
attention_tc_kernel()
{
    extern __shared__ __align__(1024) char dyn[];
    const uint32_t sb = smem_u32(dyn);
    const int tid  = threadIdx.x;
    const int wid  = tid >> 5;
    const int lane = tid & 31;

    const int qi = gridDim.x - 1 - blockIdx.x;   // heavy tiles first
    const int bh = blockIdx.y;
    const int b  = bh >> 4;
    const int h  = bh & 15;

    const int l15 = lane & 15;
    const int lhi16 = (lane >> 4) * 16;
    const int b_row = ((lane & 16) >> 1) + (lane & 7);
    const int b_khalf = (lane & 8) ? 16 : 0;
    const int tr = lane >> 2;
    const int tc2 = (lane & 3) * 2;

    const int last = qi;   // 128-key tiles: tiles 0..qi

    // ---- stage Q (hi/lo): 2 segs x 128 rows x 128B ----
#pragma unroll
    for (int i = 0; i < 8; ++i) {
        const int g = tid + 256 * i;          // 0..2047
        const int seg = g >> 10;
        const int r   = (g >> 3) & 127;
        const int gc  = g & 7;
        const uint32_t dst = sb + seg * 16384 + SWZ((uint32_t)(r * 128 + gc * 16));
        const char* src = (const char*)&g_q[((size_t)(bh * 2 + seg) * SEQ + qi * 128 + r) * HDIM] + gc * 16;
        cp_async16(dst, src);
    }
    CP_COMMIT();

    // KV stage loader: 128 keys. K[key][d] hi/lo + Vt[d][key] hi/lo.
    auto load_kv = [&](int kt, int buf) {
        const uint32_t stage = sb + 32768 + buf * 65536;
#pragma unroll
        for (int i = 0; i < 16; ++i) {
            const int g = tid + 256 * i;          // 0..4095
            const int quarter = g >> 10;          // 0=Khi 1=Klo 2=Vthi 3=Vtlo
            const int local = g & 1023;
            const int gc = local & 7;
            if (quarter < 2) {
                const int r = local >> 3;         // key 0..127
                const uint32_t dst = stage + quarter * 16384 + SWZ((uint32_t)(r * 128 + gc * 16));
                const char* src = (const char*)&g_k[((size_t)(bh * 2 + quarter) * SEQ + kt * 128 + r) * HDIM] + gc * 16;
                cp_async16(dst, src);
            } else {
                const int seg = quarter - 2;
                const int blk = local >> 9;       // key block 0/1
                const int d   = (local >> 3) & 63;
                const uint32_t dst = stage + 32768 + seg * 16384 + blk * 8192 + SWZ((uint32_t)(d * 128 + gc * 16));
                const char* src = (const char*)&g_vt[((size_t)(bh * 2 + seg) * HDIM + d) * SEQ + kt * 128 + blk * 64] + gc * 16;
                cp_async16(dst, src);
            }
        }
        CP_COMMIT();
    };

    load_kv(0, 0);
    if (last >= 1) { load_kv(1, 1); CP_WAIT(2); }
    else           { CP_WAIT(1); }
    __syncthreads();

    // ---- Q fragments into registers ----
    uint32_t qHi[4][4], qLo[4][4];
#pragma unroll
    for (int kb = 0; kb < 4; ++kb) {
        const uint32_t off = SWZ((uint32_t)((16 * wid + l15) * 128 + kb * 32 + lhi16));
        ldmx4(qHi[kb], sb + off);
        ldmx4(qLo[kb], sb + 16384 + off);
    }

    float o[8][4];
#pragma unroll
    for (int ni = 0; ni < 8; ++ni)
#pragma unroll
        for (int r = 0; r < 4; ++r) o[ni][r] = 0.f;
    float m0 = -INFINITY, m1 = -INFINITY;
    float l0 = 0.f, l1 = 0.f;

    const int rowG0 = qi * 128 + 16 * wid + tr;
    const int rowG1 = rowG0 + 8;

    int buf = 0;
    for (int kt = 0; kt <= last; ++kt) {
        if (kt < last) { CP_WAIT(1); } else { CP_WAIT(0); }
        __syncthreads();
        if (kt + 2 <= last) {
            int nb = buf + 2; if (nb >= 3) nb -= 3;
            load_kv(kt + 2, nb);
        }
        const uint32_t stage = sb + 32768 + buf * 65536;

        // ---- S = Q K^T over 128 keys (3-term split) ----
        float sacc[16][4];
#pragma unroll
        for (int ni = 0; ni < 16; ++ni)
#pragma unroll
            for (int r = 0; r < 4; ++r) sacc[ni][r] = 0.f;

#pragma unroll
        for (int kb = 0; kb < 4; ++kb) {
            const int kbb = kb * 32;
            uint32_t bHi[4], bLo[4];
#pragma unroll
            for (int nj = 0; nj < 8; ++nj) {
                const uint32_t ro = SWZ((uint32_t)((nj * 16 + b_row) * 128 + kbb + b_khalf));
                ldmx4(bHi, stage + ro);
                ldmx4(bLo, stage + 16384 + ro);
                mma16816(sacc[2 * nj],     qHi[kb], &bHi[0]);
                mma16816(sacc[2 * nj + 1], qHi[kb], &bHi[2]);
                mma16816(sacc[2 * nj],     qLo[kb], &bHi[0]);
                mma16816(sacc[2 * nj + 1], qLo[kb], &bHi[2]);
                mma16816(sacc[2 * nj],     qHi[kb], &bLo[0]);
                mma16816(sacc[2 * nj + 1], qHi[kb], &bLo[2]);
            }
        }

        // ---- scale (base-2) + causal mask (only diagonal tile crosses) ----
        if (kt == qi) {
            const int colB = kt * 128;
#pragma unroll
            for (int ni = 0; ni < 16; ++ni) {
#pragma unroll
                for (int r = 0; r < 4; ++r) {
                    const int row = (r < 2) ? rowG0 : rowG1;
                    const int col = colB + ni * 8 + tc2 + (r & 1);
                    sacc[ni][r] = (col > row) ? -INFINITY : sacc[ni][r] * SCALE2;
                }
            }
        } else {
#pragma unroll
            for (int ni = 0; ni < 16; ++ni)
#pragma unroll
                for (int r = 0; r < 4; ++r) sacc[ni][r] *= SCALE2;
        }

        // ---- row max ----
        float mx0 = -INFINITY, mx1 = -INFINITY;
#pragma unroll
        for (int ni = 0; ni < 16; ++ni) {
            mx0 = fmaxf(mx0, fmaxf(sacc[ni][0], sacc[ni][1]));
            mx1 = fmaxf(mx1, fmaxf(sacc[ni][2], sacc[ni][3]));
        }
        mx0 = fmaxf(mx0, __shfl_xor_sync(0xffffffffu, mx0, 1));
        mx0 = fmaxf(mx0, __shfl_xor_sync(0xffffffffu, mx0, 2));
        mx1 = fmaxf(mx1, __shfl_xor_sync(0xffffffffu, mx1, 1));
        mx1 = fmaxf(mx1, __shfl_xor_sync(0xffffffffu, mx1, 2));

        const float mn0 = fmaxf(m0, mx0);
        const float mn1 = fmaxf(m1, mx1);
        const float c0 = ex2f(m0 - mn0);
        const float c1 = ex2f(m1 - mn1);
        m0 = mn0;  m1 = mn1;
#pragma unroll
        for (int ni = 0; ni < 8; ++ni) {
            o[ni][0] *= c0; o[ni][1] *= c0;
            o[ni][2] *= c1; o[ni][3] *= c1;
        }

        // ---- exp2 + register P fragments + O += P V (3-term) ----
        float rs0 = 0.f, rs1 = 0.f;
#pragma unroll
        for (int kb = 0; kb < 8; ++kb) {
            float e[8];
#pragma unroll
            for (int j = 0; j < 2; ++j) {
                const int ni = 2 * kb + j;
                e[4 * j + 0] = ex2f(sacc[ni][0] - mn0);
                e[4 * j + 1] = ex2f(sacc[ni][1] - mn0);
                e[4 * j + 2] = ex2f(sacc[ni][2] - mn1);
                e[4 * j + 3] = ex2f(sacc[ni][3] - mn1);
            }
            rs0 += e[0] + e[1] + e[4] + e[5];
            rs1 += e[2] + e[3] + e[6] + e[7];

            uint32_t pHi[4], pLo[4];
#pragma unroll
            for (int j = 0; j < 2; ++j) {
                const float p0 = e[4 * j + 0], p1 = e[4 * j + 1];
                const float p2 = e[4 * j + 2], p3 = e[4 * j + 3];
                const float h0 = __bfloat162float(__float2bfloat16(p0));
                const float h1 = __bfloat162float(__float2bfloat16(p1));
                const float h2 = __bfloat162float(__float2bfloat16(p2));
                const float h3 = __bfloat162float(__float2bfloat16(p3));
                pHi[2 * j + 0] = packbf2(h0, h1);
                pHi[2 * j + 1] = packbf2(h2, h3);
                pLo[2 * j + 0] = packbf2(p0 - h0, p1 - h1);
                pLo[2 * j + 1] = packbf2(p2 - h2, p3 - h3);
            }

            const int blk = kb >> 2;
            const int kbb = (kb & 3) * 32;
            uint32_t vHi[4], vLo[4];
#pragma unroll
            for (int nj = 0; nj < 4; ++nj) {
                const uint32_t ro = SWZ((uint32_t)((nj * 16 + b_row) * 128 + kbb + b_khalf));
                const uint32_t vbase = stage + 32768 + blk * 8192 + ro;
                ldmx4(vHi, vbase);
                ldmx4(vLo, vbase + 16384);
                mma16816(o[2 * nj],     pHi, &vHi[0]);
                mma16816(o[2 * nj + 1], pHi, &vHi[2]);
                mma16816(o[2 * nj],     pLo, &vHi[0]);
                mma16816(o[2 * nj + 1], pLo, &vHi[2]);
                mma16816(o[2 * nj],     pHi, &vLo[0]);
                mma16816(o[2 * nj + 1], pHi, &vLo[2]);
            }
        }

        rs0 += __shfl_xor_sync(0xffffffffu, rs0, 1);
        rs0 += __shfl_xor_sync(0xffffffffu, rs0, 2);
        rs1 += __shfl_xor_sync(0xffffffffu, rs1, 1);
        rs1 += __shfl_xor_sync(0xffffffffu, rs1, 2);
        l0 = l0 * c0 + rs0;
        l1 = l1 * c1 + rs1;

        if (++buf >= 3) buf = 0;
    }

    // ---- normalize + write split-bf16 [hi|lo|hi] proj input ----
    const float inv0 = 1.f / l0;
    const float inv1 = 1.f / l1;
    __nv_bfloat16* r0p = g_abig + (size_t)(b * SEQ + rowG0) * KEFF;
    __nv_bfloat16* r1p = g_abig + (size_t)(b * SEQ + rowG1) * KEFF;
#pragma unroll
    for (int ni = 0; ni < 8; ++ni) {
        const int c = h * HDIM + ni * 8 + tc2;
        {
            const float p0 = o[ni][0] * inv0;
            const float p1 = o[ni][1] * inv0;
            const __nv_bfloat16 h0 = __float2bfloat16(p0);
            const __nv_bfloat16 h1 = __float2bfloat16(p1);
            const __nv_bfloat16 l0b = __float2bfloat16(p0 - __bfloat162float(h0));
            const __nv_bfloat16 l1b = __float2bfloat16(p1 - __bfloat162float(h1));
            *(__nv_bfloat162*)(r0p + c)            = __nv_bfloat162(h0, h1);
            *(__nv_bfloat162*)(r0p + CDIM + c)     = __nv_bfloat162(l0b, l1b);
            *(__nv_bfloat162*)(r0p + 2 * CDIM + c) = __nv_bfloat162(h0, h1);
        }
        {
            const float p0 = o[ni][2] * inv1;
            const float p1 = o[ni][3] * inv1;
            const __nv_bfloat16 h0 = __float2bfloat16(p0);
            const __nv_bfloat16 h1 = __float2bfloat16(p1);
            const __nv_bfloat16 l0b = __float2bfloat16(p0 - __bfloat162float(h0));
            const __nv_bfloat16 l1b = __float2bfloat16(p1 - __bfloat162float(h1));
            *(__nv_bfloat162*)(r1p + c)            = __nv_bfloat162(h0, h1);
            *(__nv_bfloat162*)(r1p + CDIM + c)     = __nv_bfloat162(l0b, l1b);
            *(__nv_bfloat162*)(r1p + 2 * CDIM + c) = __nv_bfloat162(h0, h1);
        }
    }
}

// ---------------------------------------------------------------------------
// launch
// ---------------------------------------------------------------------------
extern "C" void kernel_launch(void* const* d_in, const int* in_sizes, int n_in,
                              void* d_out, int out_size)
{
    const float* x      = (const float*)d_in[0];
    const float* w_qkv  = (const float*)d_in[1];
    const float* b_qkv  = (const float*)d_in[2];
    const float* w_proj = (const float*)d_in[3];
    const float* b_proj = (const float*)d_in[4];
    float* out = (float*)d_out;

    __nv_bfloat16* abig = nullptr; __nv_bfloat16* wqkvt = nullptr; __nv_bfloat16* wprojt = nullptr;
    cudaGetSymbolAddress((void**)&abig,   g_abig);
    cudaGetSymbolAddress((void**)&wqkvt,  g_wqkvt);
    cudaGetSymbolAddress((void**)&wprojt, g_wprojt);

    cudaFuncSetAttribute(gemm_mma_kernel,
                         cudaFuncAttributeMaxDynamicSharedMemorySize, GEMM_DYN_SMEM);
    cudaFuncSetAttribute(attention_tc_kernel,
                         cudaFuncAttributeMaxDynamicSharedMemorySize, ATT5_SMEM);

    // 0) all input prep in one launch (weights transpose+split, x split)
    prep_all_kernel<<<8192, dim3(32, 32)>>>(x, w_qkv, w_proj);

    // 1) qkv gemm: writes split Q/K (g_q,g_k) + transposed split V (g_vt)
    gemm_mma_kernel<<<dim3(C3 / 128, MROWS / 128), 256, GEMM_DYN_SMEM>>>(
        abig, wqkvt, b_qkv, out /*unused*/, C3, 1);

    // 2) tensor-core flash attention -> writes split-bf16 into g_abig
    attention_tc_kernel<<<dim3(SEQ / 128, NBH), 256, ATT5_SMEM>>>();

    // 3) out = att @ w_proj + b_proj
    gemm_mma_kernel<<<dim3(CDIM / 128, MROWS / 128), 256, GEMM_DYN_SMEM>>>(
        abig, wprojt, b_proj, out, CDIM, 0);
}